// round 6
// baseline (speedup 1.0000x reference)
#include <cuda_runtime.h>
#include <cuda_bf16.h>
#include <math.h>

#define N_NODES   3000
#define HID       64
#define MAXD      128
#define NGRP      4
#define BATCH     256
#define SEQL      50

// ---------------- scratch (device globals; no allocation) ----------------
__device__ int   g_col[N_NODES * MAXD];
__device__ int   g_deg[N_NODES];     // real degree
__device__ int   g_degp[N_NODES];    // padded to multiple of 8
__device__ __align__(16) float2 g_ca[N_NODES * MAXD];  // {.x=bitcast(col*HID), .y=coef}
__device__ __align__(16) float g_q  [N_NODES * HID];
__device__ __align__(16) float g_k  [N_NODES * HID];
__device__ __align__(16) float g_v  [N_NODES * HID];
__device__ __align__(16) float g_z0 [N_NODES * HID];
__device__ __align__(16) float g_z1 [N_NODES * HID];
__device__ __align__(16) float g_h  [N_NODES * HID];
__device__ float g_ss2[N_NODES];
__device__ float g_P  [NGRP * HID + 1];   // [0..255]=P[g,h], [256]=sum(Wp)

// ---------------- 1. build CSR from dense adj (+ zero g_P for this replay) ----------------
__global__ void build_csr(const float* __restrict__ adj) {
    int i = blockIdx.x;
    if (i == 0) {
        for (int t = threadIdx.x; t <= NGRP * HID; t += blockDim.x) g_P[t] = 0.f;
    }
    __shared__ int cnt;
    if (threadIdx.x == 0) cnt = 0;
    __syncthreads();
    const float4* row = reinterpret_cast<const float4*>(adj + (size_t)i * N_NODES);
    for (int j4 = threadIdx.x; j4 < N_NODES / 4; j4 += blockDim.x) {
        float4 f = row[j4];
        int j = j4 * 4;
        if (f.x > 0.f) { int p = atomicAdd(&cnt, 1); if (p < MAXD) g_col[i * MAXD + p] = j; }
        if (f.y > 0.f) { int p = atomicAdd(&cnt, 1); if (p < MAXD) g_col[i * MAXD + p] = j + 1; }
        if (f.z > 0.f) { int p = atomicAdd(&cnt, 1); if (p < MAXD) g_col[i * MAXD + p] = j + 2; }
        if (f.w > 0.f) { int p = atomicAdd(&cnt, 1); if (p < MAXD) g_col[i * MAXD + p] = j + 3; }
    }
    __syncthreads();
    int deg = min(cnt, MAXD);
    int degp = min((deg + 7) & ~7, MAXD);
    if (threadIdx.x == 0) { g_deg[i] = deg; g_degp[i] = degp; }
    for (int p = deg + (int)threadIdx.x; p < degp; p += blockDim.x) g_col[i * MAXD + p] = 0;
}

// ---------------- 2. q/k/v projections ----------------
__global__ __launch_bounds__(512) void qkv_kernel(
    const float* __restrict__ h_ext, int hsel,
    const float* __restrict__ Wq, const float* __restrict__ Wk, const float* __restrict__ Wv)
{
    __shared__ float sW[3][HID * HID];
    const float* hsrc = (hsel == 0) ? h_ext : g_h;
    int tid = threadIdx.y * 64 + threadIdx.x;
    for (int idx = tid; idx < HID * HID; idx += 512) {
        sW[0][idx] = Wq[idx]; sW[1][idx] = Wk[idx]; sW[2][idx] = Wv[idx];
    }
    __syncthreads();
    int t = threadIdx.x;
    int row0 = blockIdx.x * 32;
    for (int rr = threadIdx.y; rr < 32; rr += 8) {
        int gi = row0 + rr;
        if (gi >= N_NODES) continue;
        float aq = 0.f, ak = 0.f, av = 0.f;
        const float* hp = hsrc + gi * HID;
#pragma unroll
        for (int c = 0; c < HID; c++) {
            float hv = __ldg(&hp[c]);
            aq += hv * sW[0][c * 64 + t];
            ak += hv * sW[1][c * 64 + t];
            av += hv * sW[2][c * 64 + t];
        }
        g_q[gi * HID + t] = aq;
        g_k[gi * HID + t] = ak;
        g_v[gi * HID + t] = av;
    }
}

// ---------------- 3. edge scores + row softmax (warp per row, pairwise float4 dot) ----------------
__global__ __launch_bounds__(128) void edge_softmax() {
    __shared__ float sdot[4][MAXD];
    int ty = threadIdx.y;
    int i = blockIdx.x * 4 + ty;
    int lane = threadIdx.x;
    int half = lane >> 4;          // 0 or 1
    int hl = lane & 15;            // 0..15
    int deg = g_deg[i];
    int degp = g_degp[i];
    float4 qv = __ldg(reinterpret_cast<const float4*>(&g_q[i * HID + hl * 4]));
    const int* __restrict__ cp = &g_col[i * MAXD];
    for (int s = 0; s < degp; s += 2) {
        int e = s + half;
        int j = __ldg(&cp[e]);
        float4 kv = __ldg(reinterpret_cast<const float4*>(&g_k[j * HID + hl * 4]));
        float d = qv.x * kv.x + qv.y * kv.y + qv.z * kv.z + qv.w * kv.w;
        d += __shfl_xor_sync(0xffffffffu, d, 8);
        d += __shfl_xor_sync(0xffffffffu, d, 4);
        d += __shfl_xor_sync(0xffffffffu, d, 2);
        d += __shfl_xor_sync(0xffffffffu, d, 1);
        if (hl == 0) sdot[ty][e] = d;
    }
    __syncwarp();
    float vals[4];
#pragma unroll
    for (int tpass = 0; tpass < 4; tpass++) {
        int s = lane + 32 * tpass;
        vals[tpass] = (s < deg) ? sdot[ty][s] * 0.125f : -1e30f;
    }
    float m = fmaxf(fmaxf(vals[0], vals[1]), fmaxf(vals[2], vals[3]));
#pragma unroll
    for (int o = 16; o > 0; o >>= 1) m = fmaxf(m, __shfl_xor_sync(0xffffffffu, m, o));
    float sum = 0.f;
#pragma unroll
    for (int tpass = 0; tpass < 4; tpass++) {
        int s = lane + 32 * tpass;
        float e = (s < deg) ? __expf(vals[tpass] - m) : 0.f;
        vals[tpass] = e;
        sum += e;
    }
#pragma unroll
    for (int o = 16; o > 0; o >>= 1) sum += __shfl_xor_sync(0xffffffffu, sum, o);
    float inv = 1.f / sum;
#pragma unroll
    for (int tpass = 0; tpass < 4; tpass++) {
        int s = lane + 32 * tpass;
        if (s < deg)
            g_ca[i * MAXD + s] = make_float2(__int_as_float(__ldg(&cp[s]) * HID), vals[tpass] * inv);
        else if (s < degp)
            g_ca[i * MAXD + s] = make_float2(__int_as_float(0), 0.f);
    }
}

// ---------------- 4. SpMM hop: 2 warps per row, 2 edges per LDG.128 ----------------
// blockDim (32,8): 4 rows x 2 warps. Edge batches interleaved between the warp pair.
__global__ __launch_bounds__(256) void spmm_kernel(
    int zin_sel, int out_sel, int resid_sel, const float* __restrict__ resid_ext)
{
    __shared__ __align__(16) float2 sca[4][MAXD];
    __shared__ __align__(16) float4 spart[8][16];
    int wid = threadIdx.y;               // 0..7
    int r = wid >> 1;                    // row slot 0..3
    int w = wid & 1;                     // warp within pair
    int i = blockIdx.x * 4 + r;          // grid = 750 covers 3000 exactly
    int lane = threadIdx.x;
    int half = lane >> 4;
    int hl = lane & 15;
    int h4 = hl * 4;
    const float* __restrict__ zin = (zin_sel == 0) ? g_z0 : (zin_sel == 1) ? g_z1 : g_v;
    float* __restrict__ outp      = (out_sel == 0) ? g_z0 : (out_sel == 1) ? g_z1 : g_h;
    int degp = g_degp[i];
    // cooperative staging: the warp pair stages this row's packed edges
    const float2* __restrict__ cap = &g_ca[i * MAXD];
    for (int s = w * 32 + lane; s < degp; s += 64) sca[r][s] = __ldg(&cap[s]);
    __syncthreads();
    const float4* __restrict__ s4 = reinterpret_cast<const float4*>(sca[r]);
    float ax = 0.f, ay = 0.f, az = 0.f, aw = 0.f;
    for (int s = w * 8; s < degp; s += 16) {
        int q = s >> 1;
#pragma unroll
        for (int t = 0; t < 4; t++) {
            float4 e2 = s4[q + t];                 // {j_even, a_even, j_odd, a_odd}
            float cj = half ? e2.z : e2.x;
            float cc = half ? e2.w : e2.y;
            int j = __float_as_int(cj);            // pre-multiplied by HID
            float4 z = __ldg(reinterpret_cast<const float4*>(&zin[j + h4]));
            ax += cc * z.x; ay += cc * z.y; az += cc * z.z; aw += cc * z.w;
        }
    }
    // combine edge-halves within the warp
    ax += __shfl_down_sync(0xffffffffu, ax, 16);
    ay += __shfl_down_sync(0xffffffffu, ay, 16);
    az += __shfl_down_sync(0xffffffffu, az, 16);
    aw += __shfl_down_sync(0xffffffffu, aw, 16);
    if (half == 0) spart[wid][hl] = make_float4(ax, ay, az, aw);
    __syncthreads();
    // warp pair leader combines the two warp partials and writes out
    if (w == 0 && half == 0) {
        float4 pa = spart[2 * r][hl];
        float4 pb = spart[2 * r + 1][hl];
        float4 v4 = __ldg(reinterpret_cast<const float4*>(&g_v[i * HID + h4]));
        float4 rr;
        rr.x = 0.85f * (pa.x + pb.x) + 0.15f * v4.x;
        rr.y = 0.85f * (pa.y + pb.y) + 0.15f * v4.y;
        rr.z = 0.85f * (pa.z + pb.z) + 0.15f * v4.z;
        rr.w = 0.85f * (pa.w + pb.w) + 0.15f * v4.w;
        if (resid_sel == 1) {
            float4 e4 = __ldg(reinterpret_cast<const float4*>(&resid_ext[i * HID + h4]));
            rr.x += e4.x; rr.y += e4.y; rr.z += e4.z; rr.w += e4.w;
        } else if (resid_sel == 2) {
            float4 e4 = *reinterpret_cast<const float4*>(&g_h[i * HID + h4]);
            rr.x += e4.x; rr.y += e4.y; rr.z += e4.z; rr.w += e4.w;
        }
        *reinterpret_cast<float4*>(&outp[i * HID + h4]) = rr;
    }
}

// ---------------- 5. cluster softmax, ss2, P[g,h], sum(Wp) ----------------
__global__ __launch_bounds__(256) void cluster_kernel(
    const float* __restrict__ Wg, const float* __restrict__ bg, const float* __restrict__ Wp)
{
    __shared__ float sWg[HID * NGRP];
    __shared__ float sbg[NGRP];
    __shared__ float sws[256 * NGRP];
    __shared__ float sred[256];
    int tid = threadIdx.x;
    if (tid < HID * NGRP) sWg[tid] = Wg[tid];
    if (tid < NGRP) sbg[tid] = bg[tid];
    __syncthreads();
    int base = blockIdx.x * 256;
    int n = base + tid;
    float wpv = 0.f, s0 = 0.f, s1 = 0.f, s2 = 0.f, s3 = 0.f;
    if (n < N_NODES) {
        float l0 = sbg[0], l1 = sbg[1], l2 = sbg[2], l3 = sbg[3];
#pragma unroll
        for (int c = 0; c < HID; c++) {
            float hv = g_h[n * HID + c];
            l0 += hv * sWg[c * 4 + 0];
            l1 += hv * sWg[c * 4 + 1];
            l2 += hv * sWg[c * 4 + 2];
            l3 += hv * sWg[c * 4 + 3];
        }
        float m = fmaxf(fmaxf(l0, l1), fmaxf(l2, l3));
        float e0 = __expf(l0 - m), e1 = __expf(l1 - m), e2 = __expf(l2 - m), e3 = __expf(l3 - m);
        float inv = 1.f / (e0 + e1 + e2 + e3);
        s0 = e0 * inv; s1 = e1 * inv; s2 = e2 * inv; s3 = e3 * inv;
        g_ss2[n] = s0 * s0 + s1 * s1 + s2 * s2 + s3 * s3;
        wpv = Wp[n];
    }
    sws[tid * 4 + 0] = s0 * wpv;
    sws[tid * 4 + 1] = s1 * wpv;
    sws[tid * 4 + 2] = s2 * wpv;
    sws[tid * 4 + 3] = s3 * wpv;
    sred[tid] = wpv;
    __syncthreads();
    int g = tid >> 6, h = tid & 63;
    int nv = min(256, N_NODES - base);
    float acc = 0.f;
    for (int nn = 0; nn < nv; nn++)
        acc += sws[nn * 4 + g] * g_h[(base + nn) * HID + h];
    atomicAdd(&g_P[g * HID + h], acc);
    for (int s = 128; s > 0; s >>= 1) {
        __syncthreads();
        if (tid < s) sred[tid] += sred[tid + s];
    }
    __syncthreads();
    if (tid == 0) atomicAdd(&g_P[NGRP * HID], sred[0]);
}

// ---------------- 6. per-user stats + fused epilogue ----------------
__global__ __launch_bounds__(64) void finalize_kernel(
    const int* __restrict__ cate, const float* __restrict__ gamma,
    const float* __restrict__ beta, const float* __restrict__ bp, float* __restrict__ out)
{
    int b = blockIdx.x;
    int h = threadIdx.x;
    float S1 = 0.f, S2 = 0.f;
#pragma unroll 1
    for (int l = 0; l < SEQL; l++) {
        int c = cate[b * SEQL + l];
        if (c != 0) {
            float gv = g_h[c * HID + h];
            S1 += gv;
            S2 += gv * gv * g_ss2[c];
        }
    }
    const float invn = 1.f / (float)(NGRP * SEQL);
    float mean = S1 * invn;
    float var  = S2 * invn - mean * mean;
    float inv  = rsqrtf(var + 1e-5f);
    float ga = gamma[h], be = beta[h];
    float Swp = g_P[NGRP * HID];
    float bpv = bp[0];
    float k1 = inv * ga;
    float addc = be * Swp + bpv;
    float ms = mean * Swp;
#pragma unroll
    for (int g = 0; g < NGRP; g++) {
        out[(b * NGRP + g) * HID + h] = k1 * (g_P[g * HID + h] - ms) + addc;
    }
}

// ---------------- launch ----------------
extern "C" void kernel_launch(void* const* d_in, const int* in_sizes, int n_in,
                              void* d_out, int out_size)
{
    const int*   cate  = (const int*)  d_in[0];
    const float* adj   = (const float*)d_in[1];
    const float* emb   = (const float*)d_in[2];
    const float* Wq    = (const float*)d_in[3];
    const float* Wk    = (const float*)d_in[4];
    const float* Wv    = (const float*)d_in[5];
    const float* Wg    = (const float*)d_in[6];
    const float* bg    = (const float*)d_in[7];
    const float* Wp    = (const float*)d_in[8];
    const float* bp    = (const float*)d_in[9];
    const float* gamma = (const float*)d_in[10];
    const float* beta  = (const float*)d_in[11];
    float* out = (float*)d_out;

    build_csr<<<N_NODES, 128>>>(adj);

    for (int l = 0; l < 2; l++) {
        qkv_kernel<<<(N_NODES + 31) / 32, dim3(64, 8)>>>(
            emb, (l == 0) ? 0 : 1, Wq + l * HID * HID, Wk + l * HID * HID, Wv + l * HID * HID);
        edge_softmax<<<N_NODES / 4, dim3(32, 4)>>>();
        spmm_kernel<<<N_NODES / 4, dim3(32, 8)>>>(2, 0, 0, nullptr);           // z0 = f(v)
        spmm_kernel<<<N_NODES / 4, dim3(32, 8)>>>(0, 1, 0, nullptr);           // z1 = f(z0)
        spmm_kernel<<<N_NODES / 4, dim3(32, 8)>>>(1, 0, 0, nullptr);           // z0 = f(z1)
        spmm_kernel<<<N_NODES / 4, dim3(32, 8)>>>(0, 2, (l == 0) ? 1 : 2,
                                                  (l == 0) ? emb : nullptr);   // h = resid + f(z0)
    }

    cluster_kernel<<<(N_NODES + 255) / 256, 256>>>(Wg, bg, Wp);
    finalize_kernel<<<BATCH, HID>>>(cate, gamma, beta, bp, out);
}

// round 7
// speedup vs baseline: 1.2027x; 1.2027x over previous
#include <cuda_runtime.h>
#include <cuda_bf16.h>
#include <math.h>

#define N_NODES   3000
#define HID       64
#define MAXD      128
#define NGRP      4
#define BATCH     256
#define SEQL      50
#define MAGNA_GRID   148
#define ROWS_PER_BLK 21
#define MAGNA_THREADS (ROWS_PER_BLK * 32)

// ---------------- scratch (device globals; no allocation) ----------------
__device__ int   g_col[N_NODES * MAXD];
__device__ int   g_deg[N_NODES];     // real degree
__device__ int   g_degp[N_NODES];    // padded to multiple of 8
__device__ __align__(16) float g_q  [N_NODES * HID];
__device__ __align__(16) float g_k  [N_NODES * HID];
__device__ __align__(16) float g_v  [N_NODES * HID];
__device__ __align__(16) float g_z0 [N_NODES * HID];
__device__ __align__(16) float g_z1 [N_NODES * HID];
__device__ __align__(16) float g_z2 [N_NODES * HID];
__device__ __align__(16) float g_h  [N_NODES * HID];
__device__ float g_ss2[N_NODES];
__device__ float g_P  [NGRP * HID + 1];   // [0..255]=P[g,h], [256]=sum(Wp)
__device__ unsigned g_bar[8];             // grid-barrier counters (zeroed each replay)

// ---------------- grid barrier (148 blocks, one per SM -> deadlock-free) ----------------
__device__ __forceinline__ void grid_barrier(int slot) {
    __syncthreads();
    if (threadIdx.x == 0) {
        __threadfence();                       // release our writes
        atomicAdd(&g_bar[slot], 1u);
        unsigned v;
        do {
            asm volatile("ld.global.acquire.gpu.u32 %0, [%1];"
                         : "=r"(v) : "l"(&g_bar[slot]));
            if (v >= (unsigned)gridDim.x) break;
            __nanosleep(64);
        } while (true);
    }
    __syncthreads();
}

// ---------------- 1. build CSR from dense adj (+ zero accumulators/barriers) ----------------
__global__ void build_csr(const float* __restrict__ adj) {
    int i = blockIdx.x;
    if (i == 0) {
        for (int t = threadIdx.x; t <= NGRP * HID; t += blockDim.x) g_P[t] = 0.f;
        if (threadIdx.x < 8) g_bar[threadIdx.x] = 0u;
    }
    __shared__ int cnt;
    if (threadIdx.x == 0) cnt = 0;
    __syncthreads();
    const float4* row = reinterpret_cast<const float4*>(adj + (size_t)i * N_NODES);
    for (int j4 = threadIdx.x; j4 < N_NODES / 4; j4 += blockDim.x) {
        float4 f = row[j4];
        int j = j4 * 4;
        if (f.x > 0.f) { int p = atomicAdd(&cnt, 1); if (p < MAXD) g_col[i * MAXD + p] = j; }
        if (f.y > 0.f) { int p = atomicAdd(&cnt, 1); if (p < MAXD) g_col[i * MAXD + p] = j + 1; }
        if (f.z > 0.f) { int p = atomicAdd(&cnt, 1); if (p < MAXD) g_col[i * MAXD + p] = j + 2; }
        if (f.w > 0.f) { int p = atomicAdd(&cnt, 1); if (p < MAXD) g_col[i * MAXD + p] = j + 3; }
    }
    __syncthreads();
    int deg = min(cnt, MAXD);
    int degp = min((deg + 7) & ~7, MAXD);
    if (threadIdx.x == 0) { g_deg[i] = deg; g_degp[i] = degp; }
    for (int p = deg + (int)threadIdx.x; p < degp; p += blockDim.x) g_col[i * MAXD + p] = 0;
}

// ---------------- 2. q/k/v projections ----------------
__global__ __launch_bounds__(512) void qkv_kernel(
    const float* __restrict__ h_ext, int hsel,
    const float* __restrict__ Wq, const float* __restrict__ Wk, const float* __restrict__ Wv)
{
    __shared__ float sW[3][HID * HID];
    const float* hsrc = (hsel == 0) ? h_ext : g_h;
    int tid = threadIdx.y * 64 + threadIdx.x;
    for (int idx = tid; idx < HID * HID; idx += 512) {
        sW[0][idx] = Wq[idx]; sW[1][idx] = Wk[idx]; sW[2][idx] = Wv[idx];
    }
    __syncthreads();
    int t = threadIdx.x;
    int row0 = blockIdx.x * 32;
    for (int rr = threadIdx.y; rr < 32; rr += 8) {
        int gi = row0 + rr;
        if (gi >= N_NODES) continue;
        float aq = 0.f, ak = 0.f, av = 0.f;
        const float* hp = hsrc + gi * HID;
#pragma unroll
        for (int c = 0; c < HID; c++) {
            float hv = __ldg(&hp[c]);
            aq += hv * sW[0][c * 64 + t];
            ak += hv * sW[1][c * 64 + t];
            av += hv * sW[2][c * 64 + t];
        }
        g_q[gi * HID + t] = aq;
        g_k[gi * HID + t] = ak;
        g_v[gi * HID + t] = av;
    }
}

// ---------------- 3. persistent MAGNA layer: scores+softmax+4 hops ----------------
// grid = 148 (one block per SM), 21 warps/block, warp-per-row.
// Buffers: v -> z0 -> z1 -> z2 -> h (all distinct; L1-safe with __ldg).
__global__ __launch_bounds__(MAGNA_THREADS, 1) void magna_kernel(
    const float* __restrict__ resid_ext, int resid_sel, int slot_base)
{
    __shared__ __align__(16) float2 sedge[ROWS_PER_BLK][MAXD];
    int w    = threadIdx.x >> 5;
    int lane = threadIdx.x & 31;
    int half = lane >> 4;
    int hl   = lane & 15;
    int h4   = hl * 4;
    int i = blockIdx.x * ROWS_PER_BLK + w;
    bool active = (i < N_NODES);
    int deg = 0, degp = 0;
    if (active) { deg = g_deg[i]; degp = g_degp[i]; }

    // ---- phase 0: edge dots + row softmax -> smem {j*HID, coef} ----
    if (active) {
        float4 qv = *reinterpret_cast<const float4*>(&g_q[i * HID + h4]);
        const int* __restrict__ cp = &g_col[i * MAXD];
        for (int s = 0; s < degp; s += 2) {
            int e = s + half;
            int j = __ldg(&cp[e]);
            float4 kv = __ldg(reinterpret_cast<const float4*>(&g_k[j * HID + h4]));
            float d = qv.x * kv.x + qv.y * kv.y + qv.z * kv.z + qv.w * kv.w;
            d += __shfl_xor_sync(0xffffffffu, d, 8);
            d += __shfl_xor_sync(0xffffffffu, d, 4);
            d += __shfl_xor_sync(0xffffffffu, d, 2);
            d += __shfl_xor_sync(0xffffffffu, d, 1);
            if (hl == 0) sedge[w][e] = make_float2(__int_as_float(j * HID), d);
        }
        __syncwarp();
        float vals[4];
#pragma unroll
        for (int t = 0; t < 4; t++) {
            int s = lane + 32 * t;
            vals[t] = (s < deg) ? sedge[w][s].y * 0.125f : -1e30f;
        }
        float m = fmaxf(fmaxf(vals[0], vals[1]), fmaxf(vals[2], vals[3]));
#pragma unroll
        for (int o = 16; o > 0; o >>= 1) m = fmaxf(m, __shfl_xor_sync(0xffffffffu, m, o));
        float sum = 0.f;
#pragma unroll
        for (int t = 0; t < 4; t++) {
            int s = lane + 32 * t;
            float e = (s < deg) ? __expf(vals[t] - m) : 0.f;
            vals[t] = e;
            sum += e;
        }
#pragma unroll
        for (int o = 16; o > 0; o >>= 1) sum += __shfl_xor_sync(0xffffffffu, sum, o);
        float inv = 1.f / sum;
#pragma unroll
        for (int t = 0; t < 4; t++) {
            int s = lane + 32 * t;
            if (s < degp) sedge[w][s].y = (s < deg) ? vals[t] * inv : 0.f;
        }
        __syncwarp();
    }

    // ---- 4 diffusion hops ----
#pragma unroll
    for (int hop = 0; hop < 4; hop++) {
        if (hop > 0) grid_barrier(slot_base + hop - 1);
        if (active) {
            const float* __restrict__ zin =
                (hop == 0) ? g_v : (hop == 1) ? g_z0 : (hop == 2) ? g_z1 : g_z2;
            float* __restrict__ zout =
                (hop == 0) ? g_z0 : (hop == 1) ? g_z1 : (hop == 2) ? g_z2 : g_h;
            const float4* __restrict__ s4 = reinterpret_cast<const float4*>(sedge[w]);
            float ax = 0.f, ay = 0.f, az = 0.f, aw = 0.f;
            for (int s = 0; s < degp; s += 8) {
                int q = s >> 1;
#pragma unroll
                for (int t = 0; t < 4; t++) {
                    float4 e2 = s4[q + t];        // {j_even, a_even, j_odd, a_odd}
                    float cj = half ? e2.z : e2.x;
                    float cc = half ? e2.w : e2.y;
                    float4 z = __ldg(reinterpret_cast<const float4*>(&zin[__float_as_int(cj) + h4]));
                    ax += cc * z.x; ay += cc * z.y; az += cc * z.z; aw += cc * z.w;
                }
            }
            ax += __shfl_down_sync(0xffffffffu, ax, 16);
            ay += __shfl_down_sync(0xffffffffu, ay, 16);
            az += __shfl_down_sync(0xffffffffu, az, 16);
            aw += __shfl_down_sync(0xffffffffu, aw, 16);
            if (half == 0) {
                float4 v4 = __ldg(reinterpret_cast<const float4*>(&g_v[i * HID + h4]));
                float4 r;
                r.x = 0.85f * ax + 0.15f * v4.x;
                r.y = 0.85f * ay + 0.15f * v4.y;
                r.z = 0.85f * az + 0.15f * v4.z;
                r.w = 0.85f * aw + 0.15f * v4.w;
                if (hop == 3) {
                    if (resid_sel == 1) {
                        float4 e4 = __ldg(reinterpret_cast<const float4*>(&resid_ext[i * HID + h4]));
                        r.x += e4.x; r.y += e4.y; r.z += e4.z; r.w += e4.w;
                    } else {
                        float4 e4 = *reinterpret_cast<const float4*>(&g_h[i * HID + h4]);
                        r.x += e4.x; r.y += e4.y; r.z += e4.z; r.w += e4.w;
                    }
                }
                *reinterpret_cast<float4*>(&zout[i * HID + h4]) = r;
            }
        }
    }
}

// ---------------- 5. cluster softmax, ss2, P[g,h], sum(Wp) ----------------
__global__ __launch_bounds__(256) void cluster_kernel(
    const float* __restrict__ Wg, const float* __restrict__ bg, const float* __restrict__ Wp)
{
    __shared__ float sWg[HID * NGRP];
    __shared__ float sbg[NGRP];
    __shared__ float sws[256 * NGRP];
    __shared__ float sred[256];
    int tid = threadIdx.x;
    if (tid < HID * NGRP) sWg[tid] = Wg[tid];
    if (tid < NGRP) sbg[tid] = bg[tid];
    __syncthreads();
    int base = blockIdx.x * 256;
    int n = base + tid;
    float wpv = 0.f, s0 = 0.f, s1 = 0.f, s2 = 0.f, s3 = 0.f;
    if (n < N_NODES) {
        float l0 = sbg[0], l1 = sbg[1], l2 = sbg[2], l3 = sbg[3];
#pragma unroll
        for (int c = 0; c < HID; c++) {
            float hv = g_h[n * HID + c];
            l0 += hv * sWg[c * 4 + 0];
            l1 += hv * sWg[c * 4 + 1];
            l2 += hv * sWg[c * 4 + 2];
            l3 += hv * sWg[c * 4 + 3];
        }
        float m = fmaxf(fmaxf(l0, l1), fmaxf(l2, l3));
        float e0 = __expf(l0 - m), e1 = __expf(l1 - m), e2 = __expf(l2 - m), e3 = __expf(l3 - m);
        float inv = 1.f / (e0 + e1 + e2 + e3);
        s0 = e0 * inv; s1 = e1 * inv; s2 = e2 * inv; s3 = e3 * inv;
        g_ss2[n] = s0 * s0 + s1 * s1 + s2 * s2 + s3 * s3;
        wpv = Wp[n];
    }
    sws[tid * 4 + 0] = s0 * wpv;
    sws[tid * 4 + 1] = s1 * wpv;
    sws[tid * 4 + 2] = s2 * wpv;
    sws[tid * 4 + 3] = s3 * wpv;
    sred[tid] = wpv;
    __syncthreads();
    int g = tid >> 6, h = tid & 63;
    int nv = min(256, N_NODES - base);
    float acc = 0.f;
    for (int nn = 0; nn < nv; nn++)
        acc += sws[nn * 4 + g] * g_h[(base + nn) * HID + h];
    atomicAdd(&g_P[g * HID + h], acc);
    for (int s = 128; s > 0; s >>= 1) {
        __syncthreads();
        if (tid < s) sred[tid] += sred[tid + s];
    }
    __syncthreads();
    if (tid == 0) atomicAdd(&g_P[NGRP * HID], sred[0]);
}

// ---------------- 6. per-user stats + fused epilogue ----------------
__global__ __launch_bounds__(64) void finalize_kernel(
    const int* __restrict__ cate, const float* __restrict__ gamma,
    const float* __restrict__ beta, const float* __restrict__ bp, float* __restrict__ out)
{
    int b = blockIdx.x;
    int h = threadIdx.x;
    float S1 = 0.f, S2 = 0.f;
#pragma unroll 1
    for (int l = 0; l < SEQL; l++) {
        int c = cate[b * SEQL + l];
        if (c != 0) {
            float gv = g_h[c * HID + h];
            S1 += gv;
            S2 += gv * gv * g_ss2[c];
        }
    }
    const float invn = 1.f / (float)(NGRP * SEQL);
    float mean = S1 * invn;
    float var  = S2 * invn - mean * mean;
    float inv  = rsqrtf(var + 1e-5f);
    float ga = gamma[h], be = beta[h];
    float Swp = g_P[NGRP * HID];
    float bpv = bp[0];
    float k1 = inv * ga;
    float addc = be * Swp + bpv;
    float ms = mean * Swp;
#pragma unroll
    for (int g = 0; g < NGRP; g++) {
        out[(b * NGRP + g) * HID + h] = k1 * (g_P[g * HID + h] - ms) + addc;
    }
}

// ---------------- launch ----------------
extern "C" void kernel_launch(void* const* d_in, const int* in_sizes, int n_in,
                              void* d_out, int out_size)
{
    const int*   cate  = (const int*)  d_in[0];
    const float* adj   = (const float*)d_in[1];
    const float* emb   = (const float*)d_in[2];
    const float* Wq    = (const float*)d_in[3];
    const float* Wk    = (const float*)d_in[4];
    const float* Wv    = (const float*)d_in[5];
    const float* Wg    = (const float*)d_in[6];
    const float* bg    = (const float*)d_in[7];
    const float* Wp    = (const float*)d_in[8];
    const float* bp    = (const float*)d_in[9];
    const float* gamma = (const float*)d_in[10];
    const float* beta  = (const float*)d_in[11];
    float* out = (float*)d_out;

    build_csr<<<N_NODES, 128>>>(adj);

    for (int l = 0; l < 2; l++) {
        qkv_kernel<<<(N_NODES + 31) / 32, dim3(64, 8)>>>(
            emb, (l == 0) ? 0 : 1, Wq + l * HID * HID, Wk + l * HID * HID, Wv + l * HID * HID);
        magna_kernel<<<MAGNA_GRID, MAGNA_THREADS>>>(
            (l == 0) ? emb : nullptr, (l == 0) ? 1 : 2, l * 3);
    }

    cluster_kernel<<<(N_NODES + 255) / 256, 256>>>(Wg, bg, Wp);
    finalize_kernel<<<BATCH, HID>>>(cate, gamma, beta, bp, out);
}

// round 8
// speedup vs baseline: 1.3639x; 1.1340x over previous
#include <cuda_runtime.h>
#include <cuda_bf16.h>
#include <math.h>

#define N_NODES   3000
#define HID       64
#define MAXD      128
#define NGRP      4
#define BATCH     256
#define SEQL      50
#define MAGNA_GRID   148
#define ROWS_PER_BLK 21
#define MAGNA_THREADS (ROWS_PER_BLK * 32)
#define QKV_ROWS  16
#define QKV_THREADS 192

// ---------------- scratch (device globals; no allocation) ----------------
__device__ int   g_col[N_NODES * MAXD];
__device__ int   g_deg[N_NODES];     // real degree
__device__ int   g_degp[N_NODES];    // padded to multiple of 8
__device__ __align__(16) float g_q  [N_NODES * HID];
__device__ __align__(16) float g_k  [N_NODES * HID];
__device__ __align__(16) float g_v  [N_NODES * HID];
__device__ __align__(16) float g_z0 [N_NODES * HID];
__device__ __align__(16) float g_z1 [N_NODES * HID];
__device__ __align__(16) float g_z2 [N_NODES * HID];
__device__ __align__(16) float g_h  [N_NODES * HID];
__device__ float g_ss2[N_NODES];
__device__ float g_P  [NGRP * HID + 1];   // [0..255]=P[g,h], [256]=sum(Wp)
__device__ unsigned g_bar[8];             // grid-barrier counters (zeroed each replay)

// ---------------- grid barrier (148 blocks, one per SM -> deadlock-free) ----------------
__device__ __forceinline__ void grid_barrier(int slot) {
    __syncthreads();
    if (threadIdx.x == 0) {
        __threadfence();                       // release our writes
        atomicAdd(&g_bar[slot], 1u);
        unsigned v;
        do {
            asm volatile("ld.global.acquire.gpu.u32 %0, [%1];"
                         : "=r"(v) : "l"(&g_bar[slot]));
            if (v >= (unsigned)gridDim.x) break;
            __nanosleep(64);
        } while (true);
    }
    __syncthreads();
}

// ---------------- 1. build CSR from dense adj (+ zero accumulators/barriers) ----------------
__global__ void build_csr(const float* __restrict__ adj) {
    int i = blockIdx.x;
    if (i == 0) {
        for (int t = threadIdx.x; t <= NGRP * HID; t += blockDim.x) g_P[t] = 0.f;
        if (threadIdx.x < 8) g_bar[threadIdx.x] = 0u;
    }
    __shared__ int cnt;
    if (threadIdx.x == 0) cnt = 0;
    __syncthreads();
    const float4* row = reinterpret_cast<const float4*>(adj + (size_t)i * N_NODES);
    for (int j4 = threadIdx.x; j4 < N_NODES / 4; j4 += blockDim.x) {
        float4 f = row[j4];
        int j = j4 * 4;
        if (f.x > 0.f) { int p = atomicAdd(&cnt, 1); if (p < MAXD) g_col[i * MAXD + p] = j; }
        if (f.y > 0.f) { int p = atomicAdd(&cnt, 1); if (p < MAXD) g_col[i * MAXD + p] = j + 1; }
        if (f.z > 0.f) { int p = atomicAdd(&cnt, 1); if (p < MAXD) g_col[i * MAXD + p] = j + 2; }
        if (f.w > 0.f) { int p = atomicAdd(&cnt, 1); if (p < MAXD) g_col[i * MAXD + p] = j + 3; }
    }
    __syncthreads();
    int deg = min(cnt, MAXD);
    int degp = min((deg + 7) & ~7, MAXD);
    if (threadIdx.x == 0) { g_deg[i] = deg; g_degp[i] = degp; }
    for (int p = deg + (int)threadIdx.x; p < degp; p += blockDim.x) g_col[i * MAXD + p] = 0;
}

// ---------------- 2. q/k/v projections (register-blocked, LDS.128 weights) ----------------
// grid = ceil(3000/16) = 188 blocks x 192 threads.
// thread = (matrix m, col-quad q, 4-row rep). per c: 1 LDS.128 + 4 bcast LDS + 16 FFMA.
__global__ __launch_bounds__(QKV_THREADS) void qkv_kernel(
    const float* __restrict__ h_ext, int hsel,
    const float* __restrict__ Wq, const float* __restrict__ Wk, const float* __restrict__ Wv)
{
    __shared__ __align__(16) float sW[3 * HID * HID];   // 48 KB
    __shared__ float sh[QKV_ROWS][HID + 1];             // pad 65 to dodge conflicts
    const float* hsrc = (hsel == 0) ? h_ext : g_h;
    int tid = threadIdx.x;
    int base = blockIdx.x * QKV_ROWS;
    // stage weights
    for (int idx = tid; idx < HID * HID; idx += QKV_THREADS) {
        sW[idx]                 = Wq[idx];
        sW[HID * HID + idx]     = Wk[idx];
        sW[2 * HID * HID + idx] = Wv[idx];
    }
    // stage h tile
    for (int idx = tid; idx < QKV_ROWS * HID; idx += QKV_THREADS) {
        int r = idx >> 6, c = idx & 63;
        int gi = base + r;
        sh[r][c] = (gi < N_NODES) ? __ldg(&hsrc[gi * HID + c]) : 0.f;
    }
    __syncthreads();

    int slot = tid % 48;
    int m    = slot >> 4;          // matrix 0..2
    int qq   = slot & 15;          // col quad 0..15
    int rep  = tid / 48;           // 0..3
    int r0   = rep * 4;
    const float* wbase = &sW[m * HID * HID + qq * 4];
    float4 acc0 = make_float4(0.f, 0.f, 0.f, 0.f);
    float4 acc1 = acc0, acc2 = acc0, acc3 = acc0;
#pragma unroll
    for (int c = 0; c < HID; c++) {
        float4 w4 = *reinterpret_cast<const float4*>(wbase + c * HID);
        float h0 = sh[r0 + 0][c];
        float h1 = sh[r0 + 1][c];
        float h2 = sh[r0 + 2][c];
        float h3 = sh[r0 + 3][c];
        acc0.x += h0 * w4.x; acc0.y += h0 * w4.y; acc0.z += h0 * w4.z; acc0.w += h0 * w4.w;
        acc1.x += h1 * w4.x; acc1.y += h1 * w4.y; acc1.z += h1 * w4.z; acc1.w += h1 * w4.w;
        acc2.x += h2 * w4.x; acc2.y += h2 * w4.y; acc2.z += h2 * w4.z; acc2.w += h2 * w4.w;
        acc3.x += h3 * w4.x; acc3.y += h3 * w4.y; acc3.z += h3 * w4.z; acc3.w += h3 * w4.w;
    }
    float* dst = (m == 0) ? g_q : (m == 1) ? g_k : g_v;
    float4 accs[4] = {acc0, acc1, acc2, acc3};
#pragma unroll
    for (int i2 = 0; i2 < 4; i2++) {
        int gi = base + r0 + i2;
        if (gi < N_NODES)
            *reinterpret_cast<float4*>(&dst[gi * HID + qq * 4]) = accs[i2];
    }
}

// ---------------- 3. persistent MAGNA layer: scores+softmax+4 hops ----------------
__global__ __launch_bounds__(MAGNA_THREADS, 1) void magna_kernel(
    const float* __restrict__ resid_ext, int resid_sel, int slot_base)
{
    __shared__ __align__(16) float2 sedge[ROWS_PER_BLK][MAXD];
    int w    = threadIdx.x >> 5;
    int lane = threadIdx.x & 31;
    int half = lane >> 4;
    int hl   = lane & 15;
    int h4   = hl * 4;
    int i = blockIdx.x * ROWS_PER_BLK + w;
    bool active = (i < N_NODES);
    int deg = 0, degp = 0;
    if (active) { deg = g_deg[i]; degp = g_degp[i]; }

    // ---- phase 0: edge dots + row softmax -> smem {j*HID, coef} ----
    if (active) {
        float4 qv = *reinterpret_cast<const float4*>(&g_q[i * HID + h4]);
        const int* __restrict__ cp = &g_col[i * MAXD];
        for (int s = 0; s < degp; s += 2) {
            int e = s + half;
            int j = __ldg(&cp[e]);
            float4 kv = __ldg(reinterpret_cast<const float4*>(&g_k[j * HID + h4]));
            float d = qv.x * kv.x + qv.y * kv.y + qv.z * kv.z + qv.w * kv.w;
            d += __shfl_xor_sync(0xffffffffu, d, 8);
            d += __shfl_xor_sync(0xffffffffu, d, 4);
            d += __shfl_xor_sync(0xffffffffu, d, 2);
            d += __shfl_xor_sync(0xffffffffu, d, 1);
            if (hl == 0) sedge[w][e] = make_float2(__int_as_float(j * HID), d);
        }
        __syncwarp();
        float vals[4];
#pragma unroll
        for (int t = 0; t < 4; t++) {
            int s = lane + 32 * t;
            vals[t] = (s < deg) ? sedge[w][s].y * 0.125f : -1e30f;
        }
        float m = fmaxf(fmaxf(vals[0], vals[1]), fmaxf(vals[2], vals[3]));
#pragma unroll
        for (int o = 16; o > 0; o >>= 1) m = fmaxf(m, __shfl_xor_sync(0xffffffffu, m, o));
        float sum = 0.f;
#pragma unroll
        for (int t = 0; t < 4; t++) {
            int s = lane + 32 * t;
            float e = (s < deg) ? __expf(vals[t] - m) : 0.f;
            vals[t] = e;
            sum += e;
        }
#pragma unroll
        for (int o = 16; o > 0; o >>= 1) sum += __shfl_xor_sync(0xffffffffu, sum, o);
        float inv = 1.f / sum;
#pragma unroll
        for (int t = 0; t < 4; t++) {
            int s = lane + 32 * t;
            if (s < degp) sedge[w][s].y = (s < deg) ? vals[t] * inv : 0.f;
        }
        __syncwarp();
    }

    // ---- 4 diffusion hops ----
#pragma unroll
    for (int hop = 0; hop < 4; hop++) {
        if (hop > 0) grid_barrier(slot_base + hop - 1);
        if (active) {
            const float* __restrict__ zin =
                (hop == 0) ? g_v : (hop == 1) ? g_z0 : (hop == 2) ? g_z1 : g_z2;
            float* __restrict__ zout =
                (hop == 0) ? g_z0 : (hop == 1) ? g_z1 : (hop == 2) ? g_z2 : g_h;
            const float4* __restrict__ s4 = reinterpret_cast<const float4*>(sedge[w]);
            float ax = 0.f, ay = 0.f, az = 0.f, aw = 0.f;
            for (int s = 0; s < degp; s += 8) {
                int q = s >> 1;
#pragma unroll
                for (int t = 0; t < 4; t++) {
                    float4 e2 = s4[q + t];        // {j_even, a_even, j_odd, a_odd}
                    float cj = half ? e2.z : e2.x;
                    float cc = half ? e2.w : e2.y;
                    float4 z = __ldg(reinterpret_cast<const float4*>(&zin[__float_as_int(cj) + h4]));
                    ax += cc * z.x; ay += cc * z.y; az += cc * z.z; aw += cc * z.w;
                }
            }
            ax += __shfl_down_sync(0xffffffffu, ax, 16);
            ay += __shfl_down_sync(0xffffffffu, ay, 16);
            az += __shfl_down_sync(0xffffffffu, az, 16);
            aw += __shfl_down_sync(0xffffffffu, aw, 16);
            if (half == 0) {
                float4 v4 = __ldg(reinterpret_cast<const float4*>(&g_v[i * HID + h4]));
                float4 r;
                r.x = 0.85f * ax + 0.15f * v4.x;
                r.y = 0.85f * ay + 0.15f * v4.y;
                r.z = 0.85f * az + 0.15f * v4.z;
                r.w = 0.85f * aw + 0.15f * v4.w;
                if (hop == 3) {
                    if (resid_sel == 1) {
                        float4 e4 = __ldg(reinterpret_cast<const float4*>(&resid_ext[i * HID + h4]));
                        r.x += e4.x; r.y += e4.y; r.z += e4.z; r.w += e4.w;
                    } else {
                        float4 e4 = *reinterpret_cast<const float4*>(&g_h[i * HID + h4]);
                        r.x += e4.x; r.y += e4.y; r.z += e4.z; r.w += e4.w;
                    }
                }
                *reinterpret_cast<float4*>(&zout[i * HID + h4]) = r;
            }
        }
    }
}

// ---------------- 5. cluster softmax, ss2, P[g,h], sum(Wp) ----------------
__global__ __launch_bounds__(256) void cluster_kernel(
    const float* __restrict__ Wg, const float* __restrict__ bg, const float* __restrict__ Wp)
{
    __shared__ float sWg[HID * NGRP];
    __shared__ float sbg[NGRP];
    __shared__ float sws[256 * NGRP];
    __shared__ float sred[256];
    int tid = threadIdx.x;
    if (tid < HID * NGRP) sWg[tid] = Wg[tid];
    if (tid < NGRP) sbg[tid] = bg[tid];
    __syncthreads();
    int base = blockIdx.x * 256;
    int n = base + tid;
    float wpv = 0.f, s0 = 0.f, s1 = 0.f, s2 = 0.f, s3 = 0.f;
    if (n < N_NODES) {
        float l0 = sbg[0], l1 = sbg[1], l2 = sbg[2], l3 = sbg[3];
#pragma unroll
        for (int c = 0; c < HID; c++) {
            float hv = g_h[n * HID + c];
            l0 += hv * sWg[c * 4 + 0];
            l1 += hv * sWg[c * 4 + 1];
            l2 += hv * sWg[c * 4 + 2];
            l3 += hv * sWg[c * 4 + 3];
        }
        float m = fmaxf(fmaxf(l0, l1), fmaxf(l2, l3));
        float e0 = __expf(l0 - m), e1 = __expf(l1 - m), e2 = __expf(l2 - m), e3 = __expf(l3 - m);
        float inv = 1.f / (e0 + e1 + e2 + e3);
        s0 = e0 * inv; s1 = e1 * inv; s2 = e2 * inv; s3 = e3 * inv;
        g_ss2[n] = s0 * s0 + s1 * s1 + s2 * s2 + s3 * s3;
        wpv = Wp[n];
    }
    sws[tid * 4 + 0] = s0 * wpv;
    sws[tid * 4 + 1] = s1 * wpv;
    sws[tid * 4 + 2] = s2 * wpv;
    sws[tid * 4 + 3] = s3 * wpv;
    sred[tid] = wpv;
    __syncthreads();
    int g = tid >> 6, h = tid & 63;
    int nv = min(256, N_NODES - base);
    float acc = 0.f;
    for (int nn = 0; nn < nv; nn++)
        acc += sws[nn * 4 + g] * g_h[(base + nn) * HID + h];
    atomicAdd(&g_P[g * HID + h], acc);
    for (int s = 128; s > 0; s >>= 1) {
        __syncthreads();
        if (tid < s) sred[tid] += sred[tid + s];
    }
    __syncthreads();
    if (tid == 0) atomicAdd(&g_P[NGRP * HID], sred[0]);
}

// ---------------- 6. per-user stats + fused epilogue ----------------
__global__ __launch_bounds__(64) void finalize_kernel(
    const int* __restrict__ cate, const float* __restrict__ gamma,
    const float* __restrict__ beta, const float* __restrict__ bp, float* __restrict__ out)
{
    int b = blockIdx.x;
    int h = threadIdx.x;
    float S1 = 0.f, S2 = 0.f;
#pragma unroll 1
    for (int l = 0; l < SEQL; l++) {
        int c = cate[b * SEQL + l];
        if (c != 0) {
            float gv = g_h[c * HID + h];
            S1 += gv;
            S2 += gv * gv * g_ss2[c];
        }
    }
    const float invn = 1.f / (float)(NGRP * SEQL);
    float mean = S1 * invn;
    float var  = S2 * invn - mean * mean;
    float inv  = rsqrtf(var + 1e-5f);
    float ga = gamma[h], be = beta[h];
    float Swp = g_P[NGRP * HID];
    float bpv = bp[0];
    float k1 = inv * ga;
    float addc = be * Swp + bpv;
    float ms = mean * Swp;
#pragma unroll
    for (int g = 0; g < NGRP; g++) {
        out[(b * NGRP + g) * HID + h] = k1 * (g_P[g * HID + h] - ms) + addc;
    }
}

// ---------------- launch ----------------
extern "C" void kernel_launch(void* const* d_in, const int* in_sizes, int n_in,
                              void* d_out, int out_size)
{
    const int*   cate  = (const int*)  d_in[0];
    const float* adj   = (const float*)d_in[1];
    const float* emb   = (const float*)d_in[2];
    const float* Wq    = (const float*)d_in[3];
    const float* Wk    = (const float*)d_in[4];
    const float* Wv    = (const float*)d_in[5];
    const float* Wg    = (const float*)d_in[6];
    const float* bg    = (const float*)d_in[7];
    const float* Wp    = (const float*)d_in[8];
    const float* bp    = (const float*)d_in[9];
    const float* gamma = (const float*)d_in[10];
    const float* beta  = (const float*)d_in[11];
    float* out = (float*)d_out;

    build_csr<<<N_NODES, 128>>>(adj);

    int qkv_grid = (N_NODES + QKV_ROWS - 1) / QKV_ROWS;
    for (int l = 0; l < 2; l++) {
        qkv_kernel<<<qkv_grid, QKV_THREADS>>>(
            emb, (l == 0) ? 0 : 1, Wq + l * HID * HID, Wk + l * HID * HID, Wv + l * HID * HID);
        magna_kernel<<<MAGNA_GRID, MAGNA_THREADS>>>(
            (l == 0) ? emb : nullptr, (l == 0) ? 1 : 2, l * 3);
    }

    cluster_kernel<<<(N_NODES + 255) / 256, 256>>>(Wg, bg, Wp);
    finalize_kernel<<<BATCH, HID>>>(cate, gamma, beta, bp, out);
}